// round 14
// baseline (speedup 1.0000x reference)
#include <cuda_runtime.h>
#include <cuda_fp16.h>
#include <math.h>
#include <stdint.h>

typedef unsigned short u16;
typedef uint32_t u32;
typedef uint64_t u64;

#define C_    768
#define P_    1024
#define LDA1  6912           // sampled A phys row: 9 taps x 768, hi-only fp16
#define LDX   768            // g_X2 / g_blk phys row: hi-only 768
#define LDB1  6912           // conv weight row: 9 taps x 768
#define LDBF  1536           // 1x1 weight row: [blk 768 | x 768]
#define MBIG  20480
#define TM    128
#define THREADS 512
#define STG_OFF 20480        // A 16KB + B 4KB
#define DYN_OFF (3 * STG_OFF)
#define DYN_WEFF (768 * 28 * 4)   // 86016 B

// ---------------- static device scratch --------------------------------------
__device__ u16  g_X2[(size_t)MBIG * LDX];          // fp16 inputs (all 5 blocks)
__device__ u16  g_blk[(size_t)MBIG * LDX];         // fp16 block outputs
__device__ u16  g_A1[(size_t)MBIG * LDA1];         // fp16 sampled A
__device__ u16  g_B1[(size_t)C_ * LDB1];           // conv weights
__device__ u16  g_Bfin[(size_t)5 * 512 * LDBF];    // 1x1 weights padded
__device__ u16  g_Weff[(size_t)32 * LDB1];         // composed head weights fp16
__device__ float g_be[32];                         // composed head bias
__device__ float g_omx[(size_t)MBIG * 32];         // raw head outputs
__device__ float g_off[20 * 18 * P_];
__device__ float g_mask[20 * 9 * P_];
__device__ float g_scale[C_], g_shift[C_];

struct X5  { const float* p[5]; };
struct W10 { const float* a[5]; const float* b[5]; };
struct Fin { int chN[5]; int coff[5]; int nk[5]; };

// ---------------- helpers ----------------------------------------------------
__device__ __forceinline__ u32 packh2(float a, float b) {
    return (u32)__half_as_ushort(__float2half_rn(a)) |
           ((u32)__half_as_ushort(__float2half_rn(b)) << 16);
}
__device__ __forceinline__ u32 s2u(const void* p) {
    return (u32)__cvta_generic_to_shared(p);
}
__device__ __forceinline__ void cpa16(u32 s, const void* g) {
    asm volatile("cp.async.cg.shared.global [%0], [%1], 16;"
                 :: "r"(s), "l"((u64)__cvta_generic_to_global((void*)g)));
}
__device__ __forceinline__ void cpa16z(u32 s, const void* g, u32 sz) {
    asm volatile("cp.async.cg.shared.global [%0], [%1], 16, %2;"
                 :: "r"(s), "l"((u64)__cvta_generic_to_global((void*)g)), "r"(sz));
}
#define CP_COMMIT() asm volatile("cp.async.commit_group;")
#define CP_WAIT1()  asm volatile("cp.async.wait_group 1;")
#define SWZ(o) ((o) ^ (((o) >> 3) & 0x70))
#define LDSM4(r0, r1, r2, r3, addr) \
    asm volatile("ldmatrix.sync.aligned.m8n8.x4.shared.b16 {%0,%1,%2,%3}, [%4];" \
        : "=r"(r0), "=r"(r1), "=r"(r2), "=r"(r3) : "r"(addr))
#define MMA16816(d, a0, a1, a2, a3, b0, b1) \
    asm volatile("mma.sync.aligned.m16n8k16.row.col.f32.f16.f16.f32 " \
        "{%0,%1,%2,%3}, {%4,%5,%6,%7}, {%8,%9}, {%0,%1,%2,%3};" \
        : "+f"((d)[0]), "+f"((d)[1]), "+f"((d)[2]), "+f"((d)[3]) \
        : "r"(a0), "r"(a1), "r"(a2), "r"(a3), "r"(b0), "r"(b1))

// ---------------- weight / BN prep -------------------------------------------
__global__ void bconv_k(const float* __restrict__ w) {
    size_t i = (size_t)blockIdx.x * 256 + threadIdx.x;
    if (i >= (size_t)C_ * C_ * 9) return;
    int k = (int)(i % 9);
    size_t t = i / 9;
    int c = (int)(t % C_), o = (int)(t / C_);
    g_B1[(size_t)o * LDB1 + k * C_ + c] =
        __half_as_ushort(__float2half_rn(w[i]));
}

__global__ void bfin_k(W10 ws) {
    size_t i = (size_t)blockIdx.x * 256 + threadIdx.x;
    if (i >= (size_t)5 * 512 * 1536) return;
    int cc = (int)(i % 1536);
    size_t t = i / 1536;
    int j = (int)(t % 512), b = (int)(t / 512);
    int half = cc / 768, c = cc % 768;
    const int CH[5] = {30, 100, 150, 220, 268};
    float v = 0.f;
    if (j < CH[b]) {
        if (half == 0) v = ws.a[b][j * C_ + c];
        else if (b >= 2) v = ws.b[b][j * C_ + c];
    }
    g_Bfin[((size_t)b * 512 + j) * LDBF + cc] =
        __half_as_ushort(__float2half_rn(v));
}

__global__ void bnprep_k(const float* g, const float* bt, const float* mu,
                         const float* var, const float* cb) {
    int c = blockIdx.x * 256 + threadIdx.x;
    if (c >= C_) return;
    float inv = g[c] / sqrtf(var[c] + 1e-5f);
    g_scale[c] = inv;
    g_shift[c] = cb[c] * inv + bt[c] - mu[c] * inv;
}

// Weff[o][n] = sum_cout hw[o][cout] * g_B1[cout][n]
// grid 432 (n-chunks of 16), block 256 = 16 cols x 16 cout-groups of 48
__global__ void weff_k(const float* __restrict__ ow, const float* __restrict__ mw) {
    extern __shared__ float shw[];               // [768][28] then reuse as red
    int tid = threadIdx.x;
    int n0 = blockIdx.x * 16;
    for (int i = tid; i < 27 * C_; i += 256) {
        int o = i / C_, c = i % C_;
        shw[c * 28 + o] = (o < 18) ? ow[o * C_ + c] : mw[(o - 18) * C_ + c];
    }
    __syncthreads();
    int col = tid & 15, grp = tid >> 4;          // 16 groups x 48 couts
    float acc[28];
#pragma unroll
    for (int o = 0; o < 28; o++) acc[o] = 0.f;
    const u16* b1 = g_B1 + n0 + col;
#pragma unroll 4
    for (int c = grp * 48; c < grp * 48 + 48; c++) {
        float bv = __half2float(__ushort_as_half(b1[(size_t)c * LDB1]));
        const float4* h4 = (const float4*)&shw[c * 28];
#pragma unroll
        for (int j = 0; j < 7; j++) {
            float4 h = h4[j];
            acc[4 * j]     += bv * h.x;
            acc[4 * j + 1] += bv * h.y;
            acc[4 * j + 2] += bv * h.z;
            acc[4 * j + 3] += bv * h.w;
        }
    }
    __syncthreads();
    float* red = shw;                            // [grp][col][27]
#pragma unroll
    for (int o = 0; o < 27; o++) red[(grp * 16 + col) * 27 + o] = acc[o];
    __syncthreads();
#pragma unroll
    for (int s = 8; s; s >>= 1) {
        if (grp < s) {
#pragma unroll
            for (int o = 0; o < 27; o++)
                red[(grp * 16 + col) * 27 + o] +=
                    red[((grp + s) * 16 + col) * 27 + o];
        }
        __syncthreads();
    }
    if (grp == 0) {
#pragma unroll
        for (int o = 0; o < 27; o++)
            g_Weff[(size_t)o * LDB1 + n0 + col] =
                __half_as_ushort(__float2half_rn(red[col * 27 + o]));
    }
}

__global__ void beprep_k(const float* __restrict__ ow, const float* __restrict__ mw,
                         const float* __restrict__ cb) {
    int tid = threadIdx.x;                       // 256
    int o = tid >> 3, l8 = tid & 7;
    float s = 0.f;
    if (o < 27) {
        const float* wr = (o < 18) ? (ow + o * 768) : (mw + (o - 18) * 768);
        for (int c = l8; c < 768; c += 8) s += wr[c] * cb[c];
    }
#pragma unroll
    for (int d = 4; d; d >>= 1) s += __shfl_xor_sync(0xffffffffu, s, d);
    if (l8 == 0) g_be[o] = (o < 27) ? s : 0.f;
}

// ---------------- hi-only writer ---------------------------------------------
__device__ __forceinline__ void store_hi4(u32* base32, int tid, float4 v) {
    base32[2 * tid]     = packh2(v.x, v.y);
    base32[2 * tid + 1] = packh2(v.z, v.w);
}

__global__ void xsplit_k(X5 xs) {
    int row = blockIdx.x, b = blockIdx.y;
    float4 v = ((const float4*)(xs.p[b] + (size_t)row * C_))[threadIdx.x];
    u32* base32 = (u32*)(g_X2 + ((size_t)b * 4096 + row) * LDX);
    store_hi4(base32, threadIdx.x, v);
}

// ---------------- narrow head GEMM: g_omx = im2col(g_X2) @ Weff^T + be -------
__global__ void __launch_bounds__(256, 1) gemm_off() {
    extern __shared__ char sm[];
    u32 sbase = s2u(sm);
    const int tid = threadIdx.x;
    const int wid = tid >> 5, lane = tid & 31;
    const int m0 = blockIdx.x * TM;

    auto loadStage = [&](int s, int kc) {
        u32 sb = sbase + s * STG_OFF;
        u32 bbs = sb + 16384;
        int seg = kc / 12, c0 = (kc % 12) << 6;
        {
            int row = tid >> 3, c16 = tid & 7;
            u32 off = (u32)(row * 128 + c16 * 16);
            cpa16(bbs + SWZ(off),
                  g_Weff + (size_t)row * LDB1 + seg * 768 + c0 + c16 * 8);
        }
        int ky = seg / 3 - 1, kx = seg % 3 - 1;
#pragma unroll
        for (int it = 0; it < 4; it++) {
            int i = it * 256 + tid;
            int row = i >> 3, c16 = i & 7;
            int grow = m0 + row;
            int p = grow & 1023;
            int hh = (p >> 5) + ky, ww = (p & 31) + kx;
            bool ok = hh >= 0 && hh < 32 && ww >= 0 && ww < 32;
            int srow = ok ? (grow - p + (hh << 5) + ww) : 0;
            u32 off = (u32)(row * 128 + c16 * 16);
            cpa16z(sb + SWZ(off), g_X2 + (size_t)srow * LDX + c0 + c16 * 8,
                   ok ? 16u : 0u);
        }
        CP_COMMIT();
    };

    float acc[4][4];
#pragma unroll
    for (int i = 0; i < 4; i++)
#pragma unroll
        for (int q = 0; q < 4; q++) acc[i][q] = 0.f;

    loadStage(0, 0);
    loadStage(1, 1);

    for (int kc = 0; kc < 108; kc++) {
        CP_WAIT1();
        __syncthreads();
        u32 ab = sbase + (kc % 3) * STG_OFF;
        u32 bb = ab + 16384;
#pragma unroll
        for (int ks = 0; ks < 4; ks++) {
            u32 afr[4];
            int arw = wid * 16 + (lane & 15);
            u32 aoff = (u32)(arw * 128 + ks * 32 + (lane >> 4) * 16);
            LDSM4(afr[0], afr[1], afr[2], afr[3], ab + SWZ(aoff));
#pragma unroll
            for (int np2 = 0; np2 < 2; np2++) {
                int g = lane >> 3;
                int brow = np2 * 16 + ((g >> 1) & 1) * 8 + (lane & 7);
                u32 boff = (u32)(brow * 128 + ks * 32 + (g & 1) * 16);
                u32 bfr[4];
                LDSM4(bfr[0], bfr[1], bfr[2], bfr[3], bb + SWZ(boff));
                MMA16816(acc[2 * np2], afr[0], afr[1], afr[2], afr[3],
                         bfr[0], bfr[1]);
                MMA16816(acc[2 * np2 + 1], afr[0], afr[1], afr[2], afr[3],
                         bfr[2], bfr[3]);
            }
        }
        __syncthreads();
        int kl = kc + 2;
        if (kl < 108) loadStage(kl % 3, kl);
        else CP_COMMIT();
    }

    int quad = lane >> 2, qt = lane & 3;
#pragma unroll
    for (int np = 0; np < 4; np++) {
        int colb = np * 8 + 2 * qt;
#pragma unroll
        for (int hh = 0; hh < 2; hh++) {
            int row = m0 + wid * 16 + quad + hh * 8;
            g_omx[(size_t)row * 32 + colb]     = acc[np][2 * hh]     + g_be[colb];
            g_omx[(size_t)row * 32 + colb + 1] = acc[np][2 * hh + 1] + g_be[colb + 1];
        }
    }
}

// ---------------- per-row offsets + softmax ----------------------------------
__global__ void offlite_k() {
    int row = blockIdx.x * 256 + threadIdx.x;   // 0..20479
    int z = row >> 10, p = row & 1023;
    const float* src = g_omx + (size_t)row * 32;
    float res[27];
#pragma unroll
    for (int o = 0; o < 27; o++) res[o] = src[o];
#pragma unroll
    for (int o = 0; o < 18; o++) g_off[z * 18 * P_ + o * P_ + p] = res[o];
    float mx = res[18];
#pragma unroll
    for (int k = 1; k < 9; k++) mx = fmaxf(mx, res[18 + k]);
    float e[9], sum = 0.f;
#pragma unroll
    for (int k = 0; k < 9; k++) { e[k] = expf(res[18 + k] - mx); sum += e[k]; }
    float r = 1.f / sum;
#pragma unroll
    for (int k = 0; k < 9; k++) g_mask[z * 9 * P_ + p * 9 + k] = e[k] * r;
}

// ---------------- deformable sampling from fp16 g_X2 -------------------------
__device__ __forceinline__ void addtap(float4& a, const uint2* xb, int pix,
                                       int t, float w) {
    uint2 s = xb[(size_t)pix * 192 + t];
    __half2 h0 = *(__half2*)&s.x, h1 = *(__half2*)&s.y;
    float2 f0 = __half22float2(h0), f1 = __half22float2(h1);
    a.x += w * f0.x; a.y += w * f0.y; a.z += w * f1.x; a.w += w * f1.y;
}

__global__ void sample_split_k() {
    int p = blockIdx.x, k = blockIdx.y, z = blockIdx.z;
    float dy = g_off[z * 18 * P_ + (2 * k) * P_ + p];
    float dx = g_off[z * 18 * P_ + (2 * k + 1) * P_ + p];
    float m = g_mask[z * 9 * P_ + k * P_ + p];            // raw-reshape quirk
    int h = p >> 5, w = p & 31;
    float py = (float)(h - 1 + k / 3) + dy;
    float px = (float)(w - 1 + k % 3) + dx;
    float y0f = floorf(py), x0f = floorf(px);
    float wy = py - y0f, wx = px - x0f;
    int y0 = (int)y0f, x0 = (int)x0f;
    float w00 = (1.f - wy) * (1.f - wx), w01 = (1.f - wy) * wx;
    float w10 = wy * (1.f - wx),         w11 = wy * wx;
    bool vy0 = (y0 >= 0) && (y0 < 32),  vy1 = (y0 >= -1) && (y0 < 31);
    bool vx0 = (x0 >= 0) && (x0 < 32),  vx1 = (x0 >= -1) && (x0 < 31);
    const uint2* xb = (const uint2*)(g_X2 + (size_t)z * P_ * LDX);
    int t = threadIdx.x;
    float4 a = make_float4(0.f, 0.f, 0.f, 0.f);
    if (vy0 && vx0) addtap(a, xb, y0 * 32 + x0, t, w00);
    if (vy0 && vx1) addtap(a, xb, y0 * 32 + x0 + 1, t, w01);
    if (vy1 && vx0) addtap(a, xb, (y0 + 1) * 32 + x0, t, w10);
    if (vy1 && vx1) addtap(a, xb, (y0 + 1) * 32 + x0 + 1, t, w11);
    a.x *= m; a.y *= m; a.z *= m; a.w *= m;
    size_t row = (size_t)z * P_ + p;
    u32* base32 = (u32*)(g_A1 + row * LDA1 + (size_t)k * C_);
    store_hi4(base32, t, a);
}

// ---------------- mma.sync fp16 GEMM -----------------------------------------
// Template on TNF (CTA n-tile: 128 or 256). Warp tile = 32 x (TNF/4).
// kc: seg = kc/12, c0 = (kc%12)*64
// AK=3: GEMM2, A = g_A1 (seg=tap), NK=108          -> MODE 1 (TNF=128)
// AK=2: final, A = seg?g_X2:g_blk, NK=12/24        -> MODE 2 (TNF=256)
template<int AK, int MODE, int TNF>
__global__ void __launch_bounds__(THREADS, 1) gemm_mma(
    const u16* __restrict__ Bg, long ldb, int NKin, X5 xs,
    const float* __restrict__ aux, float* __restrict__ outp, Fin fin)
{
    constexpr int WN = TNF / 4;        // warp n-cols
    constexpr int NS = WN / 8;         // 8-col subtiles per warp
    constexpr int NP = NS / 2;         // 16-row ldsm groups
    constexpr int STG = 16384 + TNF * 128;
    extern __shared__ char sm[];
    u32 sbase = s2u(sm);
    const int tid = threadIdx.x;
    const int wid = tid >> 5, lane = tid & 31;
    const int wm = wid >> 2, wn = wid & 3;
    const int m0 = blockIdx.y * TM, n0 = blockIdx.x * TNF;

    int NK = NKin, chN = 0, coff = 0, bsel = 0;
    const u16* Bb0 = Bg;
    if (MODE == 2) {
        bsel = blockIdx.z;
        chN = fin.chN[bsel]; coff = fin.coff[bsel]; NK = fin.nk[bsel];
        Bb0 = Bg + (size_t)bsel * 512 * ldb;
        if (n0 >= chN) return;
    }
    const char* Bbase = (const char*)(Bb0 + (size_t)n0 * ldb);
    const long ldbb = ldb * 2;
    const int arow = tid >> 2, aq = tid & 3;      // 128 rows x 4 thr, 32B each
    int grow = m0 + (MODE == 2 ? bsel * 4096 : 0) + arow;

    auto loadStage = [&](int s, int kc) {
        u32 sb = sbase + s * STG;
        u32 bb = sb + 16384;
        int seg = kc / 12, c0 = (kc % 12) << 6;
        const char* Bgp = Bbase + (size_t)(seg * C_ + c0) * 2;
#pragma unroll
        for (int it = 0; it < TNF / 64; it++) {
            int i = it * THREADS + tid;
            int row = i >> 3, c16 = i & 7;
            u32 off = (u32)(row * 128 + c16 * 16);
            cpa16(bb + SWZ(off), Bgp + (size_t)row * ldbb + c16 * 16);
        }
        u32 off = (u32)(arow * 128 + aq * 32);
        u32 d0 = sb + SWZ(off), d1 = sb + SWZ(off + 16);
        int elem = c0 + aq * 16;
        if (AK == 3) {
            const u16* src = g_A1 + (size_t)grow * LDA1 + seg * C_ + elem;
            cpa16(d0, src);
            cpa16(d1, src + 8);
        } else {
            const u16* base = seg ? g_X2 : g_blk;
            const u16* src = base + (size_t)grow * LDX + elem;
            cpa16(d0, src);
            cpa16(d1, src + 8);
        }
        CP_COMMIT();
    };

    float acc[2][NS][4];
#pragma unroll
    for (int i = 0; i < 2; i++)
#pragma unroll
        for (int j = 0; j < NS; j++)
#pragma unroll
            for (int q = 0; q < 4; q++) acc[i][j][q] = 0.f;

    loadStage(0, 0);
    loadStage(1, 1);

    for (int kc = 0; kc < NK; kc++) {
        CP_WAIT1();
        __syncthreads();
        u32 ab = sbase + (kc % 3) * STG;
        u32 bb = ab + 16384;
#pragma unroll
        for (int ks = 0; ks < 4; ks++) {
            u32 afr[2][4];
#pragma unroll
            for (int ms = 0; ms < 2; ms++) {
                int row = wm * 32 + ms * 16 + (lane & 15);
                u32 off = (u32)(row * 128 + ks * 32 + (lane >> 4) * 16);
                LDSM4(afr[ms][0], afr[ms][1], afr[ms][2], afr[ms][3], ab + SWZ(off));
            }
#pragma unroll
            for (int np = 0; np < NP; np++) {
                int g = lane >> 3;
                int row = wn * WN + np * 16 + ((g >> 1) & 1) * 8 + (lane & 7);
                u32 off = (u32)(row * 128 + ks * 32 + (g & 1) * 16);
                u32 bfr[4];
                LDSM4(bfr[0], bfr[1], bfr[2], bfr[3], bb + SWZ(off));
#pragma unroll
                for (int ms = 0; ms < 2; ms++) {
                    MMA16816(acc[ms][2 * np], afr[ms][0], afr[ms][1], afr[ms][2],
                             afr[ms][3], bfr[0], bfr[1]);
                    MMA16816(acc[ms][2 * np + 1], afr[ms][0], afr[ms][1], afr[ms][2],
                             afr[ms][3], bfr[2], bfr[3]);
                }
            }
        }
        __syncthreads();
        int kl = kc + 2;
        if (kl < NK) loadStage(kl % 3, kl);
        else CP_COMMIT();
    }

    // epilogue
    int quad = lane >> 2, qt = lane & 3;
#pragma unroll
    for (int ms = 0; ms < 2; ms++) {
#pragma unroll
        for (int ns = 0; ns < NS; ns++) {
            int colb = n0 + wn * WN + ns * 8 + 2 * qt;
#pragma unroll
            for (int hh = 0; hh < 2; hh++) {
                int row = m0 + wm * 32 + ms * 16 + quad + hh * 8;
                float v0 = acc[ms][ns][2 * hh], v1 = acc[ms][ns][2 * hh + 1];
                if (MODE == 1) {
                    float t0 = fmaxf(v0 * g_scale[colb] + g_shift[colb], 0.f);
                    float t1 = fmaxf(v1 * g_scale[colb + 1] + g_shift[colb + 1], 0.f);
                    ((u32*)(g_blk + (size_t)row * LDX))[colb >> 1] = packh2(t0, t1);
                } else {
                    // concat is along channels: plain 4096 spatial rows
                    if (colb < chN)
                        outp[(size_t)row * C_ + coff + colb] =
                            v0 + aux[(size_t)row * C_ + coff + colb];
                    if (colb + 1 < chN)
                        outp[(size_t)row * C_ + coff + colb + 1] =
                            v1 + aux[(size_t)row * C_ + coff + colb + 1];
                }
            }
        }
    }
}

#define DYN_G2 (3 * (16384 + 128 * 128))
#define DYN_GF (3 * (16384 + 256 * 128))

// ---------------- launch -----------------------------------------------------
extern "C" void kernel_launch(void* const* d_in, const int* in_sizes, int n_in,
                              void* d_out, int out_size) {
    static u16 *pB1 = 0, *pBf = 0;
    if (!pB1) {
        cudaGetSymbolAddress((void**)&pB1, g_B1);
        cudaGetSymbolAddress((void**)&pBf, g_Bfin);
        cudaFuncSetAttribute((const void*)&gemm_mma<3, 1, 128>,
                             cudaFuncAttributeMaxDynamicSharedMemorySize, DYN_G2);
        cudaFuncSetAttribute((const void*)&gemm_mma<2, 2, 256>,
                             cudaFuncAttributeMaxDynamicSharedMemorySize, DYN_GF);
        cudaFuncSetAttribute(gemm_off,
                             cudaFuncAttributeMaxDynamicSharedMemorySize, DYN_OFF);
        cudaFuncSetAttribute(weff_k,
                             cudaFuncAttributeMaxDynamicSharedMemorySize, DYN_WEFF);
    }
    X5 xs;
    for (int i = 0; i < 5; i++) xs.p[i] = (const float*)d_in[i];
    const float* conv_w = (const float*)d_in[5];
    const float* conv_b = (const float*)d_in[6];
    const float* offw   = (const float*)d_in[7];
    const float* maskw  = (const float*)d_in[8];
    W10 ws;
    const int waIdx[5] = {0, 1, 2, 4, 6};
    for (int b = 0; b < 5; b++) {
        ws.a[b] = (const float*)d_in[13 + waIdx[b]];
        ws.b[b] = (b >= 2) ? (const float*)d_in[13 + waIdx[b] + 1] : ws.a[b];
    }
    float* out = (float*)d_out;
    Fin fin;
    const int CH[5]   = {30, 100, 150, 220, 268};
    const int COFF[5] = {0, 30, 130, 280, 500};
    for (int b = 0; b < 5; b++) {
        fin.chN[b] = CH[b]; fin.coff[b] = COFF[b]; fin.nk[b] = (b < 2) ? 12 : 24;
    }

    bconv_k<<<(int)(((size_t)C_ * C_ * 9 + 255) / 256), 256>>>(conv_w);
    bfin_k<<<(int)(((size_t)5 * 512 * 1536 + 255) / 256), 256>>>(ws);
    bnprep_k<<<3, 256>>>((const float*)d_in[9], (const float*)d_in[10],
                         (const float*)d_in[11], (const float*)d_in[12], conv_b);
    weff_k<<<432, 256, DYN_WEFF>>>(offw, maskw);
    beprep_k<<<1, 256>>>(offw, maskw, conv_b);
    xsplit_k<<<dim3(4096, 5), 192>>>(xs);

    gemm_off<<<160, 256, DYN_OFF>>>();
    offlite_k<<<80, 256>>>();
    sample_split_k<<<dim3(P_, 9, 20), 192>>>();
    gemm_mma<3, 1, 128><<<dim3(6, 160), THREADS, DYN_G2>>>(
        pB1, LDB1, 108, xs, nullptr, nullptr, fin);
    gemm_mma<2, 2, 256><<<dim3(2, 32, 5), THREADS, DYN_GF>>>(
        pBf, LDBF, 0, xs, xs.p[4], out, fin);
}

// round 15
// speedup vs baseline: 1.0555x; 1.0555x over previous
#include <cuda_runtime.h>
#include <cuda_fp16.h>
#include <math.h>
#include <stdint.h>

typedef unsigned short u16;
typedef uint32_t u32;
typedef uint64_t u64;

#define C_    768
#define P_    1024
#define LDA1  6912           // sampled A phys row: 9 taps x 768, hi-only fp16
#define LDX   768            // g_X2 / g_blk phys row: hi-only 768
#define LDB1  6912           // conv weight row: 9 taps x 768
#define LDBF  1536           // 1x1 weight row: [blk 768 | x 768]
#define MBIG  20480
#define TM    128
#define TN    256
#define THREADS 512
#define STG_BYTES 49152      // A 16KB + B 32KB
#define DYN_SMEM (3 * STG_BYTES)
#define STG_OFF 20480        // A 16KB + B 4KB
#define DYN_OFF (3 * STG_OFF)

// ---------------- static device scratch --------------------------------------
__device__ u16  g_X2[(size_t)MBIG * LDX];          // fp16 inputs (all 5 blocks)
__device__ u16  g_blk[(size_t)MBIG * LDX];         // fp16 block outputs
__device__ u16  g_A1[(size_t)MBIG * LDA1];         // fp16 sampled A
__device__ u16  g_B1[(size_t)C_ * LDB1];           // conv weights
__device__ u16  g_Bfin[(size_t)5 * 512 * LDBF];    // 1x1 weights padded
__device__ u16  g_Weff[(size_t)32 * LDB1];         // composed head weights fp16
__device__ float g_be[32];                         // composed head bias
__device__ float g_omx[(size_t)MBIG * 32];         // raw head outputs
__device__ float g_off[20 * 18 * P_];
__device__ float g_mask[20 * 9 * P_];
__device__ float g_scale[C_], g_shift[C_];

struct X5  { const float* p[5]; };
struct W10 { const float* a[5]; const float* b[5]; };
struct Fin { int chN[5]; int coff[5]; int nk[5]; };

// ---------------- helpers ----------------------------------------------------
__device__ __forceinline__ u32 packh2(float a, float b) {
    return (u32)__half_as_ushort(__float2half_rn(a)) |
           ((u32)__half_as_ushort(__float2half_rn(b)) << 16);
}
__device__ __forceinline__ u32 s2u(const void* p) {
    return (u32)__cvta_generic_to_shared(p);
}
__device__ __forceinline__ void cpa16(u32 s, const void* g) {
    asm volatile("cp.async.cg.shared.global [%0], [%1], 16;"
                 :: "r"(s), "l"((u64)__cvta_generic_to_global((void*)g)));
}
__device__ __forceinline__ void cpa16z(u32 s, const void* g, u32 sz) {
    asm volatile("cp.async.cg.shared.global [%0], [%1], 16, %2;"
                 :: "r"(s), "l"((u64)__cvta_generic_to_global((void*)g)), "r"(sz));
}
#define CP_COMMIT() asm volatile("cp.async.commit_group;")
#define CP_WAIT1()  asm volatile("cp.async.wait_group 1;")
#define SWZ(o) ((o) ^ (((o) >> 3) & 0x70))
#define LDSM4(r0, r1, r2, r3, addr) \
    asm volatile("ldmatrix.sync.aligned.m8n8.x4.shared.b16 {%0,%1,%2,%3}, [%4];" \
        : "=r"(r0), "=r"(r1), "=r"(r2), "=r"(r3) : "r"(addr))
#define MMA16816(d, a0, a1, a2, a3, b0, b1) \
    asm volatile("mma.sync.aligned.m16n8k16.row.col.f32.f16.f16.f32 " \
        "{%0,%1,%2,%3}, {%4,%5,%6,%7}, {%8,%9}, {%0,%1,%2,%3};" \
        : "+f"((d)[0]), "+f"((d)[1]), "+f"((d)[2]), "+f"((d)[3]) \
        : "r"(a0), "r"(a1), "r"(a2), "r"(a3), "r"(b0), "r"(b1))

// ---------------- weight / BN prep -------------------------------------------
__global__ void bconv_k(const float* __restrict__ w) {
    size_t i = (size_t)blockIdx.x * 256 + threadIdx.x;
    if (i >= (size_t)C_ * C_ * 9) return;
    int k = (int)(i % 9);
    size_t t = i / 9;
    int c = (int)(t % C_), o = (int)(t / C_);
    g_B1[(size_t)o * LDB1 + k * C_ + c] =
        __half_as_ushort(__float2half_rn(w[i]));
}

__global__ void bfin_k(W10 ws) {
    size_t i = (size_t)blockIdx.x * 256 + threadIdx.x;
    if (i >= (size_t)5 * 512 * 1536) return;
    int cc = (int)(i % 1536);
    size_t t = i / 1536;
    int j = (int)(t % 512), b = (int)(t / 512);
    int half = cc / 768, c = cc % 768;
    const int CH[5] = {30, 100, 150, 220, 268};
    float v = 0.f;
    if (j < CH[b]) {
        if (half == 0) v = ws.a[b][j * C_ + c];
        else if (b >= 2) v = ws.b[b][j * C_ + c];
    }
    g_Bfin[((size_t)b * 512 + j) * LDBF + cc] =
        __half_as_ushort(__float2half_rn(v));
}

__global__ void bnprep_k(const float* g, const float* bt, const float* mu,
                         const float* var, const float* cb) {
    int c = blockIdx.x * 256 + threadIdx.x;
    if (c >= C_) return;
    float inv = g[c] / sqrtf(var[c] + 1e-5f);
    g_scale[c] = inv;
    g_shift[c] = cb[c] * inv + bt[c] - mu[c] * inv;
}

// Weff[o][n] = sum_cout hw[o][cout] * g_B1[cout][n]
// grid (108, 4): 64 n-cols x 8 o-slice per block; 24KB smem, light registers
__global__ void weff_k(const float* __restrict__ ow, const float* __restrict__ mw) {
    __shared__ float shw[768 * 8];               // [c][8 o-slice]
    __shared__ float red[256 * 8];
    int tid = threadIdx.x;
    int n0 = blockIdx.x * 64;
    int og0 = blockIdx.y * 8;
    for (int i = tid; i < 768 * 8; i += 256) {
        int c = i >> 3, j = i & 7;
        int o = og0 + j;
        float v = 0.f;
        if (o < 18)      v = ow[o * C_ + c];
        else if (o < 27) v = mw[(o - 18) * C_ + c];
        shw[i] = v;
    }
    __syncthreads();
    int col = tid & 63, grp = tid >> 6;          // 4 groups x 192 couts
    float acc[8];
#pragma unroll
    for (int j = 0; j < 8; j++) acc[j] = 0.f;
    const u16* b1 = g_B1 + n0 + col;
#pragma unroll 4
    for (int c = grp * 192; c < grp * 192 + 192; c++) {
        float bv = __half2float(__ushort_as_half(b1[(size_t)c * LDB1]));
        const float4* h4 = (const float4*)&shw[c * 8];
        float4 h0 = h4[0], h1 = h4[1];
        acc[0] += bv * h0.x; acc[1] += bv * h0.y;
        acc[2] += bv * h0.z; acc[3] += bv * h0.w;
        acc[4] += bv * h1.x; acc[5] += bv * h1.y;
        acc[6] += bv * h1.z; acc[7] += bv * h1.w;
    }
#pragma unroll
    for (int j = 0; j < 8; j++) red[tid * 8 + j] = acc[j];
    __syncthreads();
    if (grp == 0) {
#pragma unroll
        for (int j = 0; j < 8; j++) {
            int o = og0 + j;
            if (o < 27) {
                float s = red[col * 8 + j] + red[(64 + col) * 8 + j] +
                          red[(128 + col) * 8 + j] + red[(192 + col) * 8 + j];
                g_Weff[(size_t)o * LDB1 + n0 + col] =
                    __half_as_ushort(__float2half_rn(s));
            }
        }
    }
}

__global__ void beprep_k(const float* __restrict__ ow, const float* __restrict__ mw,
                         const float* __restrict__ cb) {
    int tid = threadIdx.x;                       // 256
    int o = tid >> 3, l8 = tid & 7;
    float s = 0.f;
    if (o < 27) {
        const float* wr = (o < 18) ? (ow + o * 768) : (mw + (o - 18) * 768);
        for (int c = l8; c < 768; c += 8) s += wr[c] * cb[c];
    }
#pragma unroll
    for (int d = 4; d; d >>= 1) s += __shfl_xor_sync(0xffffffffu, s, d);
    if (l8 == 0) g_be[o] = (o < 27) ? s : 0.f;
}

// ---------------- hi-only writer ---------------------------------------------
__device__ __forceinline__ void store_hi4(u32* base32, int tid, float4 v) {
    base32[2 * tid]     = packh2(v.x, v.y);
    base32[2 * tid + 1] = packh2(v.z, v.w);
}

__global__ void xsplit_k(X5 xs) {
    int row = blockIdx.x, b = blockIdx.y;
    float4 v = ((const float4*)(xs.p[b] + (size_t)row * C_))[threadIdx.x];
    u32* base32 = (u32*)(g_X2 + ((size_t)b * 4096 + row) * LDX);
    store_hi4(base32, threadIdx.x, v);
}

// ---------------- narrow head GEMM: g_omx = im2col(g_X2) @ Weff^T + be -------
__global__ void __launch_bounds__(256, 1) gemm_off() {
    extern __shared__ char sm[];
    u32 sbase = s2u(sm);
    const int tid = threadIdx.x;
    const int wid = tid >> 5, lane = tid & 31;
    const int m0 = blockIdx.x * TM;

    auto loadStage = [&](int s, int kc) {
        u32 sb = sbase + s * STG_OFF;
        u32 bbs = sb + 16384;
        int seg = kc / 12, c0 = (kc % 12) << 6;
        {
            int row = tid >> 3, c16 = tid & 7;
            u32 off = (u32)(row * 128 + c16 * 16);
            cpa16(bbs + SWZ(off),
                  g_Weff + (size_t)row * LDB1 + seg * 768 + c0 + c16 * 8);
        }
        int ky = seg / 3 - 1, kx = seg % 3 - 1;
#pragma unroll
        for (int it = 0; it < 4; it++) {
            int i = it * 256 + tid;
            int row = i >> 3, c16 = i & 7;
            int grow = m0 + row;
            int p = grow & 1023;
            int hh = (p >> 5) + ky, ww = (p & 31) + kx;
            bool ok = hh >= 0 && hh < 32 && ww >= 0 && ww < 32;
            int srow = ok ? (grow - p + (hh << 5) + ww) : 0;
            u32 off = (u32)(row * 128 + c16 * 16);
            cpa16z(sb + SWZ(off), g_X2 + (size_t)srow * LDX + c0 + c16 * 8,
                   ok ? 16u : 0u);
        }
        CP_COMMIT();
    };

    float acc[4][4];
#pragma unroll
    for (int i = 0; i < 4; i++)
#pragma unroll
        for (int q = 0; q < 4; q++) acc[i][q] = 0.f;

    loadStage(0, 0);
    loadStage(1, 1);

    for (int kc = 0; kc < 108; kc++) {
        CP_WAIT1();
        __syncthreads();
        u32 ab = sbase + (kc % 3) * STG_OFF;
        u32 bb = ab + 16384;
#pragma unroll
        for (int ks = 0; ks < 4; ks++) {
            u32 afr[4];
            int arw = wid * 16 + (lane & 15);
            u32 aoff = (u32)(arw * 128 + ks * 32 + (lane >> 4) * 16);
            LDSM4(afr[0], afr[1], afr[2], afr[3], ab + SWZ(aoff));
#pragma unroll
            for (int np2 = 0; np2 < 2; np2++) {
                int g = lane >> 3;
                int brow = np2 * 16 + ((g >> 1) & 1) * 8 + (lane & 7);
                u32 boff = (u32)(brow * 128 + ks * 32 + (g & 1) * 16);
                u32 bfr[4];
                LDSM4(bfr[0], bfr[1], bfr[2], bfr[3], bb + SWZ(boff));
                MMA16816(acc[2 * np2], afr[0], afr[1], afr[2], afr[3],
                         bfr[0], bfr[1]);
                MMA16816(acc[2 * np2 + 1], afr[0], afr[1], afr[2], afr[3],
                         bfr[2], bfr[3]);
            }
        }
        __syncthreads();
        int kl = kc + 2;
        if (kl < 108) loadStage(kl % 3, kl);
        else CP_COMMIT();
    }

    int quad = lane >> 2, qt = lane & 3;
#pragma unroll
    for (int np = 0; np < 4; np++) {
        int colb = np * 8 + 2 * qt;
#pragma unroll
        for (int hh = 0; hh < 2; hh++) {
            int row = m0 + wid * 16 + quad + hh * 8;
            g_omx[(size_t)row * 32 + colb]     = acc[np][2 * hh]     + g_be[colb];
            g_omx[(size_t)row * 32 + colb + 1] = acc[np][2 * hh + 1] + g_be[colb + 1];
        }
    }
}

// ---------------- per-row offsets + softmax ----------------------------------
__global__ void offlite_k() {
    int row = blockIdx.x * 256 + threadIdx.x;   // 0..20479
    int z = row >> 10, p = row & 1023;
    const float* src = g_omx + (size_t)row * 32;
    float res[27];
#pragma unroll
    for (int o = 0; o < 27; o++) res[o] = src[o];
#pragma unroll
    for (int o = 0; o < 18; o++) g_off[z * 18 * P_ + o * P_ + p] = res[o];
    float mx = res[18];
#pragma unroll
    for (int k = 1; k < 9; k++) mx = fmaxf(mx, res[18 + k]);
    float e[9], sum = 0.f;
#pragma unroll
    for (int k = 0; k < 9; k++) { e[k] = expf(res[18 + k] - mx); sum += e[k]; }
    float r = 1.f / sum;
#pragma unroll
    for (int k = 0; k < 9; k++) g_mask[z * 9 * P_ + p * 9 + k] = e[k] * r;
}

// ---------------- deformable sampling from fp16 g_X2 -------------------------
__device__ __forceinline__ void addtap(float4& a, const uint2* xb, int pix,
                                       int t, float w) {
    uint2 s = xb[(size_t)pix * 192 + t];
    __half2 h0 = *(__half2*)&s.x, h1 = *(__half2*)&s.y;
    float2 f0 = __half22float2(h0), f1 = __half22float2(h1);
    a.x += w * f0.x; a.y += w * f0.y; a.z += w * f1.x; a.w += w * f1.y;
}

__global__ void sample_split_k() {
    int p = blockIdx.x, k = blockIdx.y, z = blockIdx.z;
    float dy = g_off[z * 18 * P_ + (2 * k) * P_ + p];
    float dx = g_off[z * 18 * P_ + (2 * k + 1) * P_ + p];
    float m = g_mask[z * 9 * P_ + k * P_ + p];            // raw-reshape quirk
    int h = p >> 5, w = p & 31;
    float py = (float)(h - 1 + k / 3) + dy;
    float px = (float)(w - 1 + k % 3) + dx;
    float y0f = floorf(py), x0f = floorf(px);
    float wy = py - y0f, wx = px - x0f;
    int y0 = (int)y0f, x0 = (int)x0f;
    float w00 = (1.f - wy) * (1.f - wx), w01 = (1.f - wy) * wx;
    float w10 = wy * (1.f - wx),         w11 = wy * wx;
    bool vy0 = (y0 >= 0) && (y0 < 32),  vy1 = (y0 >= -1) && (y0 < 31);
    bool vx0 = (x0 >= 0) && (x0 < 32),  vx1 = (x0 >= -1) && (x0 < 31);
    const uint2* xb = (const uint2*)(g_X2 + (size_t)z * P_ * LDX);
    int t = threadIdx.x;
    float4 a = make_float4(0.f, 0.f, 0.f, 0.f);
    if (vy0 && vx0) addtap(a, xb, y0 * 32 + x0, t, w00);
    if (vy0 && vx1) addtap(a, xb, y0 * 32 + x0 + 1, t, w01);
    if (vy1 && vx0) addtap(a, xb, (y0 + 1) * 32 + x0, t, w10);
    if (vy1 && vx1) addtap(a, xb, (y0 + 1) * 32 + x0 + 1, t, w11);
    a.x *= m; a.y *= m; a.z *= m; a.w *= m;
    size_t row = (size_t)z * P_ + p;
    u32* base32 = (u32*)(g_A1 + row * LDA1 + (size_t)k * C_);
    store_hi4(base32, t, a);
}

// ---------------- mma.sync fp16 GEMM (TM=128, TN=256) ------------------------
// kc: seg = kc/12, c0 = (kc%12)*64
// AK=3: GEMM2, A = g_A1 (seg=tap), NK=108          -> MODE 1
// AK=2: final, A = seg?g_X2:g_blk, NK=12/24        -> MODE 2
template<int AK, int MODE>
__global__ void __launch_bounds__(THREADS, 1) gemm_mma(
    const u16* __restrict__ Bg, long ldb, int NKin, X5 xs,
    const float* __restrict__ aux, float* __restrict__ outp, Fin fin)
{
    extern __shared__ char sm[];
    u32 sbase = s2u(sm);
    const int tid = threadIdx.x;
    const int wid = tid >> 5, lane = tid & 31;
    const int wm = wid >> 2, wn = wid & 3;
    const int m0 = blockIdx.y * TM, n0 = blockIdx.x * TN;

    int NK = NKin, chN = 0, coff = 0, bsel = 0;
    const u16* Bb0 = Bg;
    if (MODE == 2) {
        bsel = blockIdx.z;
        chN = fin.chN[bsel]; coff = fin.coff[bsel]; NK = fin.nk[bsel];
        Bb0 = Bg + (size_t)bsel * 512 * ldb;
        if (n0 >= chN) return;
    }
    const char* Bbase = (const char*)(Bb0 + (size_t)n0 * ldb);
    const long ldbb = ldb * 2;
    const int arow = tid >> 2, aq = tid & 3;      // 128 rows x 4 thr, 32B each
    int grow = m0 + (MODE == 2 ? bsel * 4096 : 0) + arow;

    auto loadStage = [&](int s, int kc) {
        u32 sb = sbase + s * STG_BYTES;
        u32 bb = sb + 16384;
        int seg = kc / 12, c0 = (kc % 12) << 6;
        const char* Bgp = Bbase + (size_t)(seg * C_ + c0) * 2;
#pragma unroll
        for (int it = 0; it < 4; it++) {
            int i = it * THREADS + tid;
            int row = i >> 3, c16 = i & 7;
            u32 off = (u32)(row * 128 + c16 * 16);
            cpa16(bb + SWZ(off), Bgp + (size_t)row * ldbb + c16 * 16);
        }
        u32 off = (u32)(arow * 128 + aq * 32);
        u32 d0 = sb + SWZ(off), d1 = sb + SWZ(off + 16);
        int elem = c0 + aq * 16;
        if (AK == 3) {
            const u16* src = g_A1 + (size_t)grow * LDA1 + seg * C_ + elem;
            cpa16(d0, src);
            cpa16(d1, src + 8);
        } else {
            const u16* base = seg ? g_X2 : g_blk;
            const u16* src = base + (size_t)grow * LDX + elem;
            cpa16(d0, src);
            cpa16(d1, src + 8);
        }
        CP_COMMIT();
    };

    float acc[2][8][4];
#pragma unroll
    for (int i = 0; i < 2; i++)
#pragma unroll
        for (int j = 0; j < 8; j++)
#pragma unroll
            for (int q = 0; q < 4; q++) acc[i][j][q] = 0.f;

    loadStage(0, 0);
    loadStage(1, 1);

    for (int kc = 0; kc < NK; kc++) {
        CP_WAIT1();
        __syncthreads();
        u32 ab = sbase + (kc % 3) * STG_BYTES;
        u32 bb = ab + 16384;
#pragma unroll
        for (int ks = 0; ks < 4; ks++) {
            u32 afr[2][4];
#pragma unroll
            for (int ms = 0; ms < 2; ms++) {
                int row = wm * 32 + ms * 16 + (lane & 15);
                u32 off = (u32)(row * 128 + ks * 32 + (lane >> 4) * 16);
                LDSM4(afr[ms][0], afr[ms][1], afr[ms][2], afr[ms][3], ab + SWZ(off));
            }
#pragma unroll
            for (int np = 0; np < 4; np++) {
                int g = lane >> 3;
                int row = wn * 64 + np * 16 + ((g >> 1) & 1) * 8 + (lane & 7);
                u32 off = (u32)(row * 128 + ks * 32 + (g & 1) * 16);
                u32 bfr[4];
                LDSM4(bfr[0], bfr[1], bfr[2], bfr[3], bb + SWZ(off));
#pragma unroll
                for (int ms = 0; ms < 2; ms++) {
                    MMA16816(acc[ms][2 * np], afr[ms][0], afr[ms][1], afr[ms][2],
                             afr[ms][3], bfr[0], bfr[1]);
                    MMA16816(acc[ms][2 * np + 1], afr[ms][0], afr[ms][1], afr[ms][2],
                             afr[ms][3], bfr[2], bfr[3]);
                }
            }
        }
        __syncthreads();
        int kl = kc + 2;
        if (kl < NK) loadStage(kl % 3, kl);
        else CP_COMMIT();
    }

    // epilogue
    int quad = lane >> 2, qt = lane & 3;
#pragma unroll
    for (int ms = 0; ms < 2; ms++) {
#pragma unroll
        for (int ns = 0; ns < 8; ns++) {
            int colb = n0 + wn * 64 + ns * 8 + 2 * qt;
#pragma unroll
            for (int hh = 0; hh < 2; hh++) {
                int row = m0 + wm * 32 + ms * 16 + quad + hh * 8;
                float v0 = acc[ms][ns][2 * hh], v1 = acc[ms][ns][2 * hh + 1];
                if (MODE == 1) {
                    float t0 = fmaxf(v0 * g_scale[colb] + g_shift[colb], 0.f);
                    float t1 = fmaxf(v1 * g_scale[colb + 1] + g_shift[colb + 1], 0.f);
                    ((u32*)(g_blk + (size_t)row * LDX))[colb >> 1] = packh2(t0, t1);
                } else {
                    // concat is along channels: plain 4096 spatial rows
                    if (colb < chN)
                        outp[(size_t)row * C_ + coff + colb] =
                            v0 + aux[(size_t)row * C_ + coff + colb];
                    if (colb + 1 < chN)
                        outp[(size_t)row * C_ + coff + colb + 1] =
                            v1 + aux[(size_t)row * C_ + coff + colb + 1];
                }
            }
        }
    }
}

// ---------------- launch -----------------------------------------------------
extern "C" void kernel_launch(void* const* d_in, const int* in_sizes, int n_in,
                              void* d_out, int out_size) {
    static u16 *pB1 = 0, *pBf = 0;
    if (!pB1) {
        cudaGetSymbolAddress((void**)&pB1, g_B1);
        cudaGetSymbolAddress((void**)&pBf, g_Bfin);
        cudaFuncSetAttribute(gemm_mma<3, 1>,
                             cudaFuncAttributeMaxDynamicSharedMemorySize, DYN_SMEM);
        cudaFuncSetAttribute(gemm_mma<2, 2>,
                             cudaFuncAttributeMaxDynamicSharedMemorySize, DYN_SMEM);
        cudaFuncSetAttribute(gemm_off,
                             cudaFuncAttributeMaxDynamicSharedMemorySize, DYN_OFF);
    }
    X5 xs;
    for (int i = 0; i < 5; i++) xs.p[i] = (const float*)d_in[i];
    const float* conv_w = (const float*)d_in[5];
    const float* conv_b = (const float*)d_in[6];
    const float* offw   = (const float*)d_in[7];
    const float* maskw  = (const float*)d_in[8];
    W10 ws;
    const int waIdx[5] = {0, 1, 2, 4, 6};
    for (int b = 0; b < 5; b++) {
        ws.a[b] = (const float*)d_in[13 + waIdx[b]];
        ws.b[b] = (b >= 2) ? (const float*)d_in[13 + waIdx[b] + 1] : ws.a[b];
    }
    float* out = (float*)d_out;
    Fin fin;
    const int CH[5]   = {30, 100, 150, 220, 268};
    const int COFF[5] = {0, 30, 130, 280, 500};
    for (int b = 0; b < 5; b++) {
        fin.chN[b] = CH[b]; fin.coff[b] = COFF[b]; fin.nk[b] = (b < 2) ? 12 : 24;
    }

    bconv_k<<<(int)(((size_t)C_ * C_ * 9 + 255) / 256), 256>>>(conv_w);
    bfin_k<<<(int)(((size_t)5 * 512 * 1536 + 255) / 256), 256>>>(ws);
    bnprep_k<<<3, 256>>>((const float*)d_in[9], (const float*)d_in[10],
                         (const float*)d_in[11], (const float*)d_in[12], conv_b);
    weff_k<<<dim3(108, 4), 256>>>(offw, maskw);
    beprep_k<<<1, 256>>>(offw, maskw, conv_b);
    xsplit_k<<<dim3(4096, 5), 192>>>(xs);

    gemm_off<<<160, 256, DYN_OFF>>>();
    offlite_k<<<80, 256>>>();
    sample_split_k<<<dim3(P_, 9, 20), 192>>>();
    gemm_mma<3, 1><<<dim3(3, 160), THREADS, DYN_SMEM>>>(
        pB1, LDB1, 108, xs, nullptr, nullptr, fin);
    gemm_mma<2, 2><<<dim3(2, 32, 5), THREADS, DYN_SMEM>>>(
        pBf, LDBF, 0, xs, xs.p[4], out, fin);
}

// round 16
// speedup vs baseline: 1.0883x; 1.0311x over previous
#include <cuda_runtime.h>
#include <cuda_fp16.h>
#include <math.h>
#include <stdint.h>

typedef unsigned short u16;
typedef uint32_t u32;
typedef uint64_t u64;

#define C_    768
#define P_    1024
#define LDA1  6912           // sampled A phys row: 9 taps x 768, hi-only fp16
#define LDX   768            // g_X2 / g_blk phys row: hi-only 768
#define LDB1  6912           // conv weight row: 9 taps x 768
#define LDBF  1536           // 1x1 weight row: [blk 768 | x 768]
#define MBIG  20480
#define TM    128
#define TN    256
#define THREADS 512
#define STG_BYTES 49152      // A 16KB + B 32KB
#define DYN_SMEM (4 * STG_BYTES)
#define STG_OFF 20480        // A 16KB + B 4KB
#define DYN_OFF (3 * STG_OFF)

// ---------------- static device scratch --------------------------------------
__device__ u16  g_X2[(size_t)MBIG * LDX];          // fp16 inputs (all 5 blocks)
__device__ u16  g_blk[(size_t)MBIG * LDX];         // fp16 block outputs
__device__ u16  g_A1[(size_t)MBIG * LDA1];         // fp16 sampled A
__device__ u16  g_B1[(size_t)C_ * LDB1];           // conv weights
__device__ u16  g_Bfin[(size_t)5 * 512 * LDBF];    // 1x1 weights padded
__device__ u16  g_Weff[(size_t)32 * LDB1];         // composed head weights fp16
__device__ float g_be[32];                         // composed head bias
__device__ float g_off[20 * 18 * P_];
__device__ float g_mask[20 * 9 * P_];
__device__ float g_scale[C_], g_shift[C_];

struct X5  { const float* p[5]; };
struct W10 { const float* a[5]; const float* b[5]; };
struct Fin { int chN[5]; int coff[5]; int nk[5]; };

// ---------------- helpers ----------------------------------------------------
__device__ __forceinline__ u32 packh2(float a, float b) {
    return (u32)__half_as_ushort(__float2half_rn(a)) |
           ((u32)__half_as_ushort(__float2half_rn(b)) << 16);
}
__device__ __forceinline__ u32 s2u(const void* p) {
    return (u32)__cvta_generic_to_shared(p);
}
__device__ __forceinline__ void cpa16(u32 s, const void* g) {
    asm volatile("cp.async.cg.shared.global [%0], [%1], 16;"
                 :: "r"(s), "l"((u64)__cvta_generic_to_global((void*)g)));
}
__device__ __forceinline__ void cpa16z(u32 s, const void* g, u32 sz) {
    asm volatile("cp.async.cg.shared.global [%0], [%1], 16, %2;"
                 :: "r"(s), "l"((u64)__cvta_generic_to_global((void*)g)), "r"(sz));
}
#define CP_COMMIT() asm volatile("cp.async.commit_group;")
#define CP_WAIT1()  asm volatile("cp.async.wait_group 1;")
#define CP_WAIT2()  asm volatile("cp.async.wait_group 2;")
#define SWZ(o) ((o) ^ (((o) >> 3) & 0x70))
#define LDSM4(r0, r1, r2, r3, addr) \
    asm volatile("ldmatrix.sync.aligned.m8n8.x4.shared.b16 {%0,%1,%2,%3}, [%4];" \
        : "=r"(r0), "=r"(r1), "=r"(r2), "=r"(r3) : "r"(addr))
#define MMA16816(d, a0, a1, a2, a3, b0, b1) \
    asm volatile("mma.sync.aligned.m16n8k16.row.col.f32.f16.f16.f32 " \
        "{%0,%1,%2,%3}, {%4,%5,%6,%7}, {%8,%9}, {%0,%1,%2,%3};" \
        : "+f"((d)[0]), "+f"((d)[1]), "+f"((d)[2]), "+f"((d)[3]) \
        : "r"(a0), "r"(a1), "r"(a2), "r"(a3), "r"(b0), "r"(b1))

// ---------------- weight / BN prep -------------------------------------------
__global__ void bconv_k(const float* __restrict__ w) {
    size_t i = (size_t)blockIdx.x * 256 + threadIdx.x;
    if (i >= (size_t)C_ * C_ * 9) return;
    int k = (int)(i % 9);
    size_t t = i / 9;
    int c = (int)(t % C_), o = (int)(t / C_);
    g_B1[(size_t)o * LDB1 + k * C_ + c] =
        __half_as_ushort(__float2half_rn(w[i]));
}

__global__ void bfin_k(W10 ws) {
    size_t i = (size_t)blockIdx.x * 256 + threadIdx.x;
    if (i >= (size_t)5 * 512 * 1536) return;
    int cc = (int)(i % 1536);
    size_t t = i / 1536;
    int j = (int)(t % 512), b = (int)(t / 512);
    int half = cc / 768, c = cc % 768;
    const int CH[5] = {30, 100, 150, 220, 268};
    float v = 0.f;
    if (j < CH[b]) {
        if (half == 0) v = ws.a[b][j * C_ + c];
        else if (b >= 2) v = ws.b[b][j * C_ + c];
    }
    g_Bfin[((size_t)b * 512 + j) * LDBF + cc] =
        __half_as_ushort(__float2half_rn(v));
}

__global__ void bnprep_k(const float* g, const float* bt, const float* mu,
                         const float* var, const float* cb) {
    int c = blockIdx.x * 256 + threadIdx.x;
    if (c >= C_) return;
    float inv = g[c] / sqrtf(var[c] + 1e-5f);
    g_scale[c] = inv;
    g_shift[c] = cb[c] * inv + bt[c] - mu[c] * inv;
}

// Weff[o][n] = sum_cout hw[o][cout] * g_B1[cout][n]
// grid (216, 7): 32 n-cols x 4 o-slice; 8 cout-groups of 96; 1512 blocks
__global__ void weff_k(const float* __restrict__ ow, const float* __restrict__ mw) {
    __shared__ float shw[768 * 4];
    __shared__ float red[256 * 4];
    int tid = threadIdx.x;
    int n0 = blockIdx.x * 32;
    int og0 = blockIdx.y * 4;
    for (int i = tid; i < 768 * 4; i += 256) {
        int c = i >> 2, j = i & 3;
        int o = og0 + j;
        float v = 0.f;
        if (o < 18)      v = ow[o * C_ + c];
        else if (o < 27) v = mw[(o - 18) * C_ + c];
        shw[i] = v;
    }
    __syncthreads();
    int col = tid & 31, grp = tid >> 5;          // 8 groups x 96 couts
    float acc[4] = {0.f, 0.f, 0.f, 0.f};
    const u16* b1 = g_B1 + n0 + col;
#pragma unroll 4
    for (int c = grp * 96; c < grp * 96 + 96; c++) {
        float bv = __half2float(__ushort_as_half(b1[(size_t)c * LDB1]));
        const float4* h4 = (const float4*)&shw[c * 4];
        float4 h = h4[0];
        acc[0] += bv * h.x; acc[1] += bv * h.y;
        acc[2] += bv * h.z; acc[3] += bv * h.w;
    }
#pragma unroll
    for (int j = 0; j < 4; j++) red[tid * 4 + j] = acc[j];
    __syncthreads();
#pragma unroll
    for (int s = 4; s; s >>= 1) {
        if (grp < s) {
#pragma unroll
            for (int j = 0; j < 4; j++)
                red[(grp * 32 + col) * 4 + j] +=
                    red[((grp + s) * 32 + col) * 4 + j];
        }
        __syncthreads();
    }
    if (grp == 0) {
#pragma unroll
        for (int j = 0; j < 4; j++) {
            int o = og0 + j;
            if (o < 27)
                g_Weff[(size_t)o * LDB1 + n0 + col] =
                    __half_as_ushort(__float2half_rn(red[col * 4 + j]));
        }
    }
}

__global__ void beprep_k(const float* __restrict__ ow, const float* __restrict__ mw,
                         const float* __restrict__ cb) {
    int tid = threadIdx.x;                       // 256
    int o = tid >> 3, l8 = tid & 7;
    float s = 0.f;
    if (o < 27) {
        const float* wr = (o < 18) ? (ow + o * 768) : (mw + (o - 18) * 768);
        for (int c = l8; c < 768; c += 8) s += wr[c] * cb[c];
    }
#pragma unroll
    for (int d = 4; d; d >>= 1) s += __shfl_xor_sync(0xffffffffu, s, d);
    if (l8 == 0) g_be[o] = (o < 27) ? s : 0.f;
}

// ---------------- hi-only writer ---------------------------------------------
__device__ __forceinline__ void store_hi4(u32* base32, int tid, float4 v) {
    base32[2 * tid]     = packh2(v.x, v.y);
    base32[2 * tid + 1] = packh2(v.z, v.w);
}

__global__ void xsplit_k(X5 xs) {
    int row = blockIdx.x, b = blockIdx.y;
    float4 v = ((const float4*)(xs.p[b] + (size_t)row * C_))[threadIdx.x];
    u32* base32 = (u32*)(g_X2 + ((size_t)b * 4096 + row) * LDX);
    store_hi4(base32, threadIdx.x, v);
}

// ---------------- head GEMM + fused offsets/softmax epilogue -----------------
__global__ void __launch_bounds__(256, 1) gemm_off() {
    extern __shared__ char sm[];
    u32 sbase = s2u(sm);
    const int tid = threadIdx.x;
    const int wid = tid >> 5, lane = tid & 31;
    const int m0 = blockIdx.x * TM;

    auto loadStage = [&](int s, int kc) {
        u32 sb = sbase + s * STG_OFF;
        u32 bbs = sb + 16384;
        int seg = kc / 12, c0 = (kc % 12) << 6;
        {
            int row = tid >> 3, c16 = tid & 7;
            u32 off = (u32)(row * 128 + c16 * 16);
            cpa16(bbs + SWZ(off),
                  g_Weff + (size_t)row * LDB1 + seg * 768 + c0 + c16 * 8);
        }
        int ky = seg / 3 - 1, kx = seg % 3 - 1;
#pragma unroll
        for (int it = 0; it < 4; it++) {
            int i = it * 256 + tid;
            int row = i >> 3, c16 = i & 7;
            int grow = m0 + row;
            int p = grow & 1023;
            int hh = (p >> 5) + ky, ww = (p & 31) + kx;
            bool ok = hh >= 0 && hh < 32 && ww >= 0 && ww < 32;
            int srow = ok ? (grow - p + (hh << 5) + ww) : 0;
            u32 off = (u32)(row * 128 + c16 * 16);
            cpa16z(sb + SWZ(off), g_X2 + (size_t)srow * LDX + c0 + c16 * 8,
                   ok ? 16u : 0u);
        }
        CP_COMMIT();
    };

    float acc[4][4];
#pragma unroll
    for (int i = 0; i < 4; i++)
#pragma unroll
        for (int q = 0; q < 4; q++) acc[i][q] = 0.f;

    loadStage(0, 0);
    loadStage(1, 1);

    for (int kc = 0; kc < 108; kc++) {
        CP_WAIT1();
        __syncthreads();
        u32 ab = sbase + (kc % 3) * STG_OFF;
        u32 bb = ab + 16384;
#pragma unroll
        for (int ks = 0; ks < 4; ks++) {
            u32 afr[4];
            int arw = wid * 16 + (lane & 15);
            u32 aoff = (u32)(arw * 128 + ks * 32 + (lane >> 4) * 16);
            LDSM4(afr[0], afr[1], afr[2], afr[3], ab + SWZ(aoff));
#pragma unroll
            for (int np2 = 0; np2 < 2; np2++) {
                int g = lane >> 3;
                int brow = np2 * 16 + ((g >> 1) & 1) * 8 + (lane & 7);
                u32 boff = (u32)(brow * 128 + ks * 32 + (g & 1) * 16);
                u32 bfr[4];
                LDSM4(bfr[0], bfr[1], bfr[2], bfr[3], bb + SWZ(boff));
                MMA16816(acc[2 * np2], afr[0], afr[1], afr[2], afr[3],
                         bfr[0], bfr[1]);
                MMA16816(acc[2 * np2 + 1], afr[0], afr[1], afr[2], afr[3],
                         bfr[2], bfr[3]);
            }
        }
        __syncthreads();
        int kl = kc + 2;
        if (kl < 108) loadStage(kl % 3, kl);
        else CP_COMMIT();
    }

    // fused epilogue: stage accs to smem, then per-row offsets + softmax
    float* om = (float*)sm;                      // [128][33] padded
    int quad = lane >> 2, qt = lane & 3;
#pragma unroll
    for (int np = 0; np < 4; np++) {
        int colb = np * 8 + 2 * qt;
#pragma unroll
        for (int hh = 0; hh < 2; hh++) {
            int lr = wid * 16 + quad + hh * 8;
            om[lr * 33 + colb]     = acc[np][2 * hh]     + g_be[colb];
            om[lr * 33 + colb + 1] = acc[np][2 * hh + 1] + g_be[colb + 1];
        }
    }
    __syncthreads();
    if (tid < 128) {
        int grow = m0 + tid;
        int z = grow >> 10, p = grow & 1023;
        const float* src = om + tid * 33;
        float res[27];
#pragma unroll
        for (int o = 0; o < 27; o++) res[o] = src[o];
#pragma unroll
        for (int o = 0; o < 18; o++) g_off[z * 18 * P_ + o * P_ + p] = res[o];
        float mx = res[18];
#pragma unroll
        for (int k = 1; k < 9; k++) mx = fmaxf(mx, res[18 + k]);
        float e[9], sum = 0.f;
#pragma unroll
        for (int k = 0; k < 9; k++) { e[k] = expf(res[18 + k] - mx); sum += e[k]; }
        float r = 1.f / sum;
#pragma unroll
        for (int k = 0; k < 9; k++) g_mask[z * 9 * P_ + p * 9 + k] = e[k] * r;
    }
}

// ---------------- deformable sampling from fp16 g_X2 -------------------------
__device__ __forceinline__ void addtap(float4& a, const uint2* xb, int pix,
                                       int t, float w) {
    uint2 s = xb[(size_t)pix * 192 + t];
    __half2 h0 = *(__half2*)&s.x, h1 = *(__half2*)&s.y;
    float2 f0 = __half22float2(h0), f1 = __half22float2(h1);
    a.x += w * f0.x; a.y += w * f0.y; a.z += w * f1.x; a.w += w * f1.y;
}

__global__ void sample_split_k() {
    int p = blockIdx.x, k = blockIdx.y, z = blockIdx.z;
    float dy = g_off[z * 18 * P_ + (2 * k) * P_ + p];
    float dx = g_off[z * 18 * P_ + (2 * k + 1) * P_ + p];
    float m = g_mask[z * 9 * P_ + k * P_ + p];            // raw-reshape quirk
    int h = p >> 5, w = p & 31;
    float py = (float)(h - 1 + k / 3) + dy;
    float px = (float)(w - 1 + k % 3) + dx;
    float y0f = floorf(py), x0f = floorf(px);
    float wy = py - y0f, wx = px - x0f;
    int y0 = (int)y0f, x0 = (int)x0f;
    float w00 = (1.f - wy) * (1.f - wx), w01 = (1.f - wy) * wx;
    float w10 = wy * (1.f - wx),         w11 = wy * wx;
    bool vy0 = (y0 >= 0) && (y0 < 32),  vy1 = (y0 >= -1) && (y0 < 31);
    bool vx0 = (x0 >= 0) && (x0 < 32),  vx1 = (x0 >= -1) && (x0 < 31);
    const uint2* xb = (const uint2*)(g_X2 + (size_t)z * P_ * LDX);
    int t = threadIdx.x;
    float4 a = make_float4(0.f, 0.f, 0.f, 0.f);
    if (vy0 && vx0) addtap(a, xb, y0 * 32 + x0, t, w00);
    if (vy0 && vx1) addtap(a, xb, y0 * 32 + x0 + 1, t, w01);
    if (vy1 && vx0) addtap(a, xb, (y0 + 1) * 32 + x0, t, w10);
    if (vy1 && vx1) addtap(a, xb, (y0 + 1) * 32 + x0 + 1, t, w11);
    a.x *= m; a.y *= m; a.z *= m; a.w *= m;
    size_t row = (size_t)z * P_ + p;
    u32* base32 = (u32*)(g_A1 + row * LDA1 + (size_t)k * C_);
    store_hi4(base32, t, a);
}

// ---------------- mma.sync fp16 GEMM (TM=128, TN=256, 4-stage) ---------------
// kc: seg = kc/12, c0 = (kc%12)*64
// AK=3: GEMM2, A = g_A1 (seg=tap), NK=108          -> MODE 1
// AK=2: final, A = seg?g_X2:g_blk, NK=12/24        -> MODE 2
template<int AK, int MODE>
__global__ void __launch_bounds__(THREADS, 1) gemm_mma(
    const u16* __restrict__ Bg, long ldb, int NKin, X5 xs,
    const float* __restrict__ aux, float* __restrict__ outp, Fin fin)
{
    extern __shared__ char sm[];
    u32 sbase = s2u(sm);
    const int tid = threadIdx.x;
    const int wid = tid >> 5, lane = tid & 31;
    const int wm = wid >> 2, wn = wid & 3;
    const int m0 = blockIdx.y * TM, n0 = blockIdx.x * TN;

    int NK = NKin, chN = 0, coff = 0, bsel = 0;
    const u16* Bb0 = Bg;
    if (MODE == 2) {
        bsel = blockIdx.z;
        chN = fin.chN[bsel]; coff = fin.coff[bsel]; NK = fin.nk[bsel];
        Bb0 = Bg + (size_t)bsel * 512 * ldb;
        if (n0 >= chN) return;
    }
    const char* Bbase = (const char*)(Bb0 + (size_t)n0 * ldb);
    const long ldbb = ldb * 2;
    const int arow = tid >> 2, aq = tid & 3;      // 128 rows x 4 thr, 32B each
    int grow = m0 + (MODE == 2 ? bsel * 4096 : 0) + arow;

    auto loadStage = [&](int s, int kc) {
        u32 sb = sbase + s * STG_BYTES;
        u32 bb = sb + 16384;
        int seg = kc / 12, c0 = (kc % 12) << 6;
        const char* Bgp = Bbase + (size_t)(seg * C_ + c0) * 2;
#pragma unroll
        for (int it = 0; it < 4; it++) {
            int i = it * THREADS + tid;
            int row = i >> 3, c16 = i & 7;
            u32 off = (u32)(row * 128 + c16 * 16);
            cpa16(bb + SWZ(off), Bgp + (size_t)row * ldbb + c16 * 16);
        }
        u32 off = (u32)(arow * 128 + aq * 32);
        u32 d0 = sb + SWZ(off), d1 = sb + SWZ(off + 16);
        int elem = c0 + aq * 16;
        if (AK == 3) {
            const u16* src = g_A1 + (size_t)grow * LDA1 + seg * C_ + elem;
            cpa16(d0, src);
            cpa16(d1, src + 8);
        } else {
            const u16* base = seg ? g_X2 : g_blk;
            const u16* src = base + (size_t)grow * LDX + elem;
            cpa16(d0, src);
            cpa16(d1, src + 8);
        }
        CP_COMMIT();
    };

    float acc[2][8][4];
#pragma unroll
    for (int i = 0; i < 2; i++)
#pragma unroll
        for (int j = 0; j < 8; j++)
#pragma unroll
            for (int q = 0; q < 4; q++) acc[i][j][q] = 0.f;

    loadStage(0, 0);
    loadStage(1, 1);
    loadStage(2, 2);

    for (int kc = 0; kc < NK; kc++) {
        CP_WAIT2();
        __syncthreads();
        u32 ab = sbase + (kc % 4) * STG_BYTES;
        u32 bb = ab + 16384;
#pragma unroll
        for (int ks = 0; ks < 4; ks++) {
            u32 afr[2][4];
#pragma unroll
            for (int ms = 0; ms < 2; ms++) {
                int row = wm * 32 + ms * 16 + (lane & 15);
                u32 off = (u32)(row * 128 + ks * 32 + (lane >> 4) * 16);
                LDSM4(afr[ms][0], afr[ms][1], afr[ms][2], afr[ms][3], ab + SWZ(off));
            }
#pragma unroll
            for (int np = 0; np < 4; np++) {
                int g = lane >> 3;
                int row = wn * 64 + np * 16 + ((g >> 1) & 1) * 8 + (lane & 7);
                u32 off = (u32)(row * 128 + ks * 32 + (g & 1) * 16);
                u32 bfr[4];
                LDSM4(bfr[0], bfr[1], bfr[2], bfr[3], bb + SWZ(off));
#pragma unroll
                for (int ms = 0; ms < 2; ms++) {
                    MMA16816(acc[ms][2 * np], afr[ms][0], afr[ms][1], afr[ms][2],
                             afr[ms][3], bfr[0], bfr[1]);
                    MMA16816(acc[ms][2 * np + 1], afr[ms][0], afr[ms][1], afr[ms][2],
                             afr[ms][3], bfr[2], bfr[3]);
                }
            }
        }
        __syncthreads();
        int kl = kc + 3;
        if (kl < NK) loadStage(kl % 4, kl);
        else CP_COMMIT();
    }

    // epilogue
    int quad = lane >> 2, qt = lane & 3;
#pragma unroll
    for (int ms = 0; ms < 2; ms++) {
#pragma unroll
        for (int ns = 0; ns < 8; ns++) {
            int colb = n0 + wn * 64 + ns * 8 + 2 * qt;
#pragma unroll
            for (int hh = 0; hh < 2; hh++) {
                int row = m0 + wm * 32 + ms * 16 + quad + hh * 8;
                float v0 = acc[ms][ns][2 * hh], v1 = acc[ms][ns][2 * hh + 1];
                if (MODE == 1) {
                    float t0 = fmaxf(v0 * g_scale[colb] + g_shift[colb], 0.f);
                    float t1 = fmaxf(v1 * g_scale[colb + 1] + g_shift[colb + 1], 0.f);
                    ((u32*)(g_blk + (size_t)row * LDX))[colb >> 1] = packh2(t0, t1);
                } else {
                    // concat is along channels: plain 4096 spatial rows
                    if (colb < chN)
                        outp[(size_t)row * C_ + coff + colb] =
                            v0 + aux[(size_t)row * C_ + coff + colb];
                    if (colb + 1 < chN)
                        outp[(size_t)row * C_ + coff + colb + 1] =
                            v1 + aux[(size_t)row * C_ + coff + colb + 1];
                }
            }
        }
    }
}

// ---------------- launch -----------------------------------------------------
extern "C" void kernel_launch(void* const* d_in, const int* in_sizes, int n_in,
                              void* d_out, int out_size) {
    static u16 *pB1 = 0, *pBf = 0;
    static cudaStream_t s1, s2;
    static cudaEvent_t eF, e1, e2;
    if (!pB1) {
        cudaGetSymbolAddress((void**)&pB1, g_B1);
        cudaGetSymbolAddress((void**)&pBf, g_Bfin);
        cudaFuncSetAttribute(gemm_mma<3, 1>,
                             cudaFuncAttributeMaxDynamicSharedMemorySize, DYN_SMEM);
        cudaFuncSetAttribute(gemm_mma<2, 2>,
                             cudaFuncAttributeMaxDynamicSharedMemorySize, DYN_SMEM);
        cudaFuncSetAttribute(gemm_off,
                             cudaFuncAttributeMaxDynamicSharedMemorySize, DYN_OFF);
        cudaStreamCreateWithFlags(&s1, cudaStreamNonBlocking);
        cudaStreamCreateWithFlags(&s2, cudaStreamNonBlocking);
        cudaEventCreateWithFlags(&eF, cudaEventDisableTiming);
        cudaEventCreateWithFlags(&e1, cudaEventDisableTiming);
        cudaEventCreateWithFlags(&e2, cudaEventDisableTiming);
    }
    X5 xs;
    for (int i = 0; i < 5; i++) xs.p[i] = (const float*)d_in[i];
    const float* conv_w = (const float*)d_in[5];
    const float* conv_b = (const float*)d_in[6];
    const float* offw   = (const float*)d_in[7];
    const float* maskw  = (const float*)d_in[8];
    W10 ws;
    const int waIdx[5] = {0, 1, 2, 4, 6};
    for (int b = 0; b < 5; b++) {
        ws.a[b] = (const float*)d_in[13 + waIdx[b]];
        ws.b[b] = (b >= 2) ? (const float*)d_in[13 + waIdx[b] + 1] : ws.a[b];
    }
    float* out = (float*)d_out;
    Fin fin;
    const int CH[5]   = {30, 100, 150, 220, 268};
    const int COFF[5] = {0, 30, 130, 280, 500};
    for (int b = 0; b < 5; b++) {
        fin.chN[b] = CH[b]; fin.coff[b] = COFF[b]; fin.nk[b] = (b < 2) ? 12 : 24;
    }

    // fork prep work across streams
    cudaEventRecord(eF, 0);
    cudaStreamWaitEvent(s1, eF, 0);
    cudaStreamWaitEvent(s2, eF, 0);

    bconv_k<<<(int)(((size_t)C_ * C_ * 9 + 255) / 256), 256>>>(conv_w);
    weff_k<<<dim3(216, 7), 256>>>(offw, maskw);
    beprep_k<<<1, 256>>>(offw, maskw, conv_b);

    xsplit_k<<<dim3(4096, 5), 192, 0, s1>>>(xs);

    bfin_k<<<(int)(((size_t)5 * 512 * 1536 + 255) / 256), 256, 0, s2>>>(ws);
    bnprep_k<<<3, 256, 0, s2>>>((const float*)d_in[9], (const float*)d_in[10],
                                (const float*)d_in[11], (const float*)d_in[12],
                                conv_b);

    cudaEventRecord(e1, s1);
    cudaStreamWaitEvent(0, e1, 0);

    gemm_off<<<160, 256, DYN_OFF>>>();
    sample_split_k<<<dim3(P_, 9, 20), 192>>>();

    cudaEventRecord(e2, s2);
    cudaStreamWaitEvent(0, e2, 0);

    gemm_mma<3, 1><<<dim3(3, 160), THREADS, DYN_SMEM>>>(
        pB1, LDB1, 108, xs, nullptr, nullptr, fin);
    gemm_mma<2, 2><<<dim3(2, 32, 5), THREADS, DYN_SMEM>>>(
        pBf, LDBF, 0, xs, xs.p[4], out, fin);
}